// round 16
// baseline (speedup 1.0000x reference)
#include <cuda_runtime.h>
#include <cuda_bf16.h>
#include <cstdint>

#define NN 100000
#define EE 1600000
#define PP 200000
#define NTILES 782   // ceil(NN/128)
#define NB 98        // ceil(NN/1024) scan blocks

// Scratch (allocation-free rule: __device__ globals)
__device__ float g_h [NN * 64];   // node embedding after MLP
__device__ float g_u [NN * 64];   // h @ (A+C)
__device__ float g_v [NN * 64];   // h @ (A+D)
// CSR scratch
__device__ int g_deg[NN + 1];
__device__ int g_cur[NN + 1];
__device__ int g_off[NN + 1];
__device__ int g_adj[EE];
__device__ int g_blksum[NB];
__device__ int g_blkoff[NB];

// ---------------------------------------------------------------------------
// CSR build: zero -> count -> scan(3) -> fill
__global__ void k_zero() {
    int i = blockIdx.x * blockDim.x + threadIdx.x;
    if (i <= NN) { g_deg[i] = 0; g_cur[i] = 0; }
}

__global__ void __launch_bounds__(256) k_count(const int* __restrict__ ei) {
    int e = blockIdx.x * blockDim.x + threadIdx.x;
    if (e < EE) atomicAdd(&g_deg[ei[EE + e]], 1);
}

__global__ void __launch_bounds__(1024) k_scan1() {
    __shared__ int s[1024];
    int t = threadIdx.x;
    int i = blockIdx.x * 1024 + t;
    int v = (i < NN) ? g_deg[i] : 0;
    s[t] = v;
    __syncthreads();
    #pragma unroll
    for (int o = 1; o < 1024; o <<= 1) {
        int tv = (t >= o) ? s[t - o] : 0;
        __syncthreads();
        s[t] += tv;
        __syncthreads();
    }
    if (i < NN) g_off[i] = s[t] - v;          // block-local exclusive
    if (t == 1023) g_blksum[blockIdx.x] = s[t];
}

// single-warp shfl scan over the 98 block sums (was a 9us serial loop)
__global__ void k_scan2() {
    int l = threadIdx.x;                       // 0..31
    int v[4];
    #pragma unroll
    for (int t = 0; t < 4; t++) {
        int b = l * 4 + t;
        v[t] = (b < NB) ? g_blksum[b] : 0;
    }
    int tot = v[0] + v[1] + v[2] + v[3];
    int pre = tot;
    #pragma unroll
    for (int o = 1; o < 32; o <<= 1) {
        int n = __shfl_up_sync(0xffffffffu, pre, o);
        if (l >= o) pre += n;
    }
    pre -= tot;                                // exclusive
    int run = pre;
    #pragma unroll
    for (int t = 0; t < 4; t++) {
        int b = l * 4 + t;
        if (b < NB) g_blkoff[b] = run;
        run += v[t];
    }
}

__global__ void k_scan3() {
    int i = blockIdx.x * blockDim.x + threadIdx.x;
    if (i < NN) g_off[i] += g_blkoff[i >> 10];
    if (i == 0) g_off[NN] = EE;
}

__global__ void __launch_bounds__(256) k_fill(const int* __restrict__ ei) {
    int e = blockIdx.x * blockDim.x + threadIdx.x;
    if (e >= EE) return;
    int src = ei[e];
    int dst = ei[EE + e];
    int pos = atomicAdd(&g_cur[dst], 1);
    g_adj[g_off[dst] + pos] = src;
}

// ---------------------------------------------------------------------------
// shared MMA helpers
__device__ __forceinline__ void split_pack(float fx, float fy, uint32_t& hi, uint32_t& lo) {
    __nv_bfloat16 hx = __float2bfloat16(fx);
    __nv_bfloat16 hy = __float2bfloat16(fy);
    __nv_bfloat16 lx = __float2bfloat16(fx - __bfloat162float(hx));
    __nv_bfloat16 ly = __float2bfloat16(fy - __bfloat162float(hy));
    __nv_bfloat162 h2; h2.x = hx; h2.y = hy;
    __nv_bfloat162 l2; l2.x = lx; l2.y = ly;
    hi = *reinterpret_cast<uint32_t*>(&h2);
    lo = *reinterpret_cast<uint32_t*>(&l2);
}

__device__ __forceinline__ void split_sts(unsigned char* sm, int offH, int offL,
                                          int byte_off, float f) {
    __nv_bfloat16 h = __float2bfloat16(f);
    __nv_bfloat16 l = __float2bfloat16(f - __bfloat162float(h));
    *reinterpret_cast<__nv_bfloat16*>(sm + offH + byte_off) = h;
    *reinterpret_cast<__nv_bfloat16*>(sm + offL + byte_off) = l;
}

#define MMA16816(c0, c1, c2, c3, a, b0, b1)                                  \
    asm volatile(                                                            \
        "mma.sync.aligned.m16n8k16.row.col.f32.bf16.bf16.f32 "              \
        "{%0,%1,%2,%3}, {%4,%5,%6,%7}, {%8,%9}, {%0,%1,%2,%3};"             \
        : "+f"(c0), "+f"(c1), "+f"(c2), "+f"(c3)                             \
        : "r"((a)[0]), "r"((a)[1]), "r"((a)[2]), "r"((a)[3]),                \
          "r"(b0), "r"(b1))

// ===========================================================================
// K2: FUSED aggregation + node chain. Each warp CSR-aggregates its 16 A-rows
// (half-warp per node, shfl-broadcast adj) straight into registers ->
// split_pack -> private smem A-tile, then runs the 4-GEMM register-chained
// MMA pipeline. No g_h0 round-trip; gather (LSU) and MMA (tensor) phases of
// different warps overlap inside one kernel.
// ===========================================================================

#define MOFF_W1H 0
#define MOFF_W1L 9216
#define MOFF_W2H 18432
#define MOFF_W2L 27648
#define MOFF_ACH 36864
#define MOFF_ACL 46080
#define MOFF_ADH 55296
#define MOFF_ADL 64512
#define MOFF_A   73728
#define MOFF_B1  110592
#define MOFF_B2  110848
#define MLP_SMEM 111104

#define MMA_LAYER(D, WH, WL)                                                 \
    _Pragma("unroll")                                                        \
    for (int nt = 0; nt < 8; nt++) {                                         \
        int n = nt * 8 + grp;                                                \
        _Pragma("unroll")                                                    \
        for (int ks = 0; ks < 4; ks++) {                                     \
            int kb = ks * 8 + tig;                                           \
            uint32_t bh0 = (WH)[n * 36 + kb], bh1 = (WH)[n * 36 + kb + 4];   \
            uint32_t bl0 = (WL)[n * 36 + kb], bl1 = (WL)[n * 36 + kb + 4];   \
            MMA16816(D[nt].x, D[nt].y, D[nt].z, D[nt].w, ah[ks], bh0, bh1);  \
            MMA16816(D[nt].x, D[nt].y, D[nt].z, D[nt].w, ah[ks], bl0, bl1);  \
            MMA16816(D[nt].x, D[nt].y, D[nt].z, D[nt].w, al[ks], bh0, bh1);  \
        }                                                                    \
    }

#define REPACK_FRAGS(D)                                                      \
    _Pragma("unroll")                                                        \
    for (int ks = 0; ks < 4; ks++) {                                         \
        split_pack(D[2*ks].x,   D[2*ks].y,   ah[ks][0], al[ks][0]);          \
        split_pack(D[2*ks].z,   D[2*ks].w,   ah[ks][1], al[ks][1]);          \
        split_pack(D[2*ks+1].x, D[2*ks+1].y, ah[ks][2], al[ks][2]);          \
        split_pack(D[2*ks+1].z, D[2*ks+1].w, ah[ks][3], al[ks][3]);          \
    }

#define STORE_ROWS(dst, D)                                                   \
    _Pragma("unroll")                                                        \
    for (int nt = 0; nt < 8; nt++) {                                         \
        int cbase = nt * 8 + tig * 2;                                        \
        if (nodeA < NN)                                                      \
            *reinterpret_cast<float2*>(&dst[nodeA * 64 + cbase]) =           \
                make_float2(D[nt].x, D[nt].y);                               \
        if (nodeB < NN)                                                      \
            *reinterpret_cast<float2*>(&dst[nodeB * 64 + cbase]) =           \
                make_float2(D[nt].z, D[nt].w);                               \
    }

__global__ void __launch_bounds__(256) k_mlp_uv_mma(
    const float* __restrict__ x,
    const float* __restrict__ w1, const float* __restrict__ b1,
    const float* __restrict__ w2, const float* __restrict__ b2,
    const float* __restrict__ dw1)
{
    extern __shared__ unsigned char sm[];
    int tid  = threadIdx.x;
    int wid  = tid >> 5;
    int lane = tid & 31;

    for (int i = tid; i < 4096; i += 256) {
        int n = i & 63, k = i >> 6;
        int bo = n * 144 + k * 2;
        float fa = dw1[k * 64 + n];
        split_sts(sm, MOFF_W1H, MOFF_W1L, bo, w1[k * 64 + n]);
        split_sts(sm, MOFF_W2H, MOFF_W2L, bo, w2[k * 64 + n]);
        split_sts(sm, MOFF_ACH, MOFF_ACL, bo, fa + dw1[(128 + k) * 64 + n]);
        split_sts(sm, MOFF_ADH, MOFF_ADL, bo, fa + dw1[(192 + k) * 64 + n]);
    }
    if (tid < 64) {
        reinterpret_cast<float*>(sm + MOFF_B1)[tid] = b1[tid];
        reinterpret_cast<float*>(sm + MOFF_B2)[tid] = b2[tid];
    }
    __syncthreads();

    const uint32_t* W1H = reinterpret_cast<const uint32_t*>(sm + MOFF_W1H);
    const uint32_t* W1L = reinterpret_cast<const uint32_t*>(sm + MOFF_W1L);
    const uint32_t* W2H = reinterpret_cast<const uint32_t*>(sm + MOFF_W2H);
    const uint32_t* W2L = reinterpret_cast<const uint32_t*>(sm + MOFF_W2L);
    const uint32_t* ACH = reinterpret_cast<const uint32_t*>(sm + MOFF_ACH);
    const uint32_t* ACL = reinterpret_cast<const uint32_t*>(sm + MOFF_ACL);
    const uint32_t* ADH = reinterpret_cast<const uint32_t*>(sm + MOFF_ADH);
    const uint32_t* ADL = reinterpret_cast<const uint32_t*>(sm + MOFF_ADL);
    const float* sb1 = reinterpret_cast<const float*>(sm + MOFF_B1);
    const float* sb2 = reinterpret_cast<const float*>(sm + MOFF_B2);

    unsigned char* Awarp = sm + MOFF_A + wid * 4608;
    const uint32_t* AH = reinterpret_cast<const uint32_t*>(Awarp);
    const uint32_t* AL = reinterpret_cast<const uint32_t*>(Awarp + 2304);

    int grp = lane >> 2;
    int tig = lane & 3;
    int half = lane >> 4;
    int c    = lane & 15;
    unsigned hm = 0xFFFFu << (lane & 16);
    const float4* x4 = reinterpret_cast<const float4*>(x);

    for (int tile = blockIdx.x; tile < NTILES; tile += gridDim.x) {
        // ---- fused CSR aggregation -> A-tile staging ----
        #pragma unroll
        for (int t = 0; t < 8; t++) {
            int rw = t * 2 + half;
            int node = tile * 128 + wid * 16 + rw;
            int nc = node < NN ? node : NN - 1;
            float4 acc = x4[nc * 16 + c];
            acc.x += acc.x; acc.y += acc.y; acc.z += acc.z; acc.w += acc.w;
            int off0 = g_off[nc];
            int off1 = g_off[nc + 1];
            for (int base = off0; base < off1; base += 16) {
                int idxv = (base + c < off1) ? g_adj[base + c] : 0;
                int cnt  = off1 - base; if (cnt > 16) cnt = 16;
                #pragma unroll 4
                for (int tt = 0; tt < cnt; tt++) {
                    int s = __shfl_sync(hm, idxv, tt, 16);
                    float4 v = x4[s * 16 + c];
                    acc.x += v.x; acc.y += v.y; acc.z += v.z; acc.w += v.w;
                }
            }
            uint32_t h0, l0, h1, l1;
            split_pack(acc.x, acc.y, h0, l0);
            split_pack(acc.z, acc.w, h1, l1);
            *reinterpret_cast<uint2*>(Awarp + rw * 144 + c * 8)        = make_uint2(h0, h1);
            *reinterpret_cast<uint2*>(Awarp + 2304 + rw * 144 + c * 8) = make_uint2(l0, l1);
        }
        __syncwarp();

        uint32_t ah[4][4], al[4][4];
        #pragma unroll
        for (int ks = 0; ks < 4; ks++) {
            int k0 = ks * 8 + tig;
            ah[ks][0] = AH[ grp      * 36 + k0];
            ah[ks][1] = AH[(grp + 8) * 36 + k0];
            ah[ks][2] = AH[ grp      * 36 + k0 + 4];
            ah[ks][3] = AH[(grp + 8) * 36 + k0 + 4];
            al[ks][0] = AL[ grp      * 36 + k0];
            al[ks][1] = AL[(grp + 8) * 36 + k0];
            al[ks][2] = AL[ grp      * 36 + k0 + 4];
            al[ks][3] = AL[(grp + 8) * 36 + k0 + 4];
        }
        __syncwarp();   // fragments hoisted before next tile overwrites Awarp

        int nodeA = tile * 128 + wid * 16 + grp;
        int nodeB = nodeA + 8;
        float4 D[8];

        #pragma unroll
        for (int nt = 0; nt < 8; nt++) {
            int cbase = nt * 8 + tig * 2;
            float bx = sb1[cbase], by = sb1[cbase + 1];
            D[nt] = make_float4(bx, by, bx, by);
        }
        MMA_LAYER(D, W1H, W1L)
        #pragma unroll
        for (int nt = 0; nt < 8; nt++) {
            D[nt].x = fmaxf(D[nt].x, 0.0f); D[nt].y = fmaxf(D[nt].y, 0.0f);
            D[nt].z = fmaxf(D[nt].z, 0.0f); D[nt].w = fmaxf(D[nt].w, 0.0f);
        }
        REPACK_FRAGS(D)

        #pragma unroll
        for (int nt = 0; nt < 8; nt++) {
            int cbase = nt * 8 + tig * 2;
            float bx = sb2[cbase], by = sb2[cbase + 1];
            D[nt] = make_float4(bx, by, bx, by);
        }
        MMA_LAYER(D, W2H, W2L)
        #pragma unroll
        for (int nt = 0; nt < 8; nt++) {
            D[nt].x = fmaxf(D[nt].x, 0.0f); D[nt].y = fmaxf(D[nt].y, 0.0f);
            D[nt].z = fmaxf(D[nt].z, 0.0f); D[nt].w = fmaxf(D[nt].w, 0.0f);
        }
        STORE_ROWS(g_h, D)
        REPACK_FRAGS(D)

        #pragma unroll
        for (int nt = 0; nt < 8; nt++) D[nt] = make_float4(0.f, 0.f, 0.f, 0.f);
        MMA_LAYER(D, ACH, ACL)
        STORE_ROWS(g_u, D)

        #pragma unroll
        for (int nt = 0; nt < 8; nt++) D[nt] = make_float4(0.f, 0.f, 0.f, 0.f);
        MMA_LAYER(D, ADH, ADL)
        STORE_ROWS(g_v, D)
    }
}

// ===========================================================================
// K3: pair decoder (unchanged from R15).
// ===========================================================================

#define OFF_PH  0
#define OFF_PL  18432
#define OFF_BH  36864
#define OFF_BL  46080
#define OFF_DW2 55296
#define OFF_DB1 55552
#define PAIR_SMEM 55808

__global__ void __launch_bounds__(256) k_pair_mma(
    const int* __restrict__ idx,
    const float* __restrict__ dw1, const float* __restrict__ db1,
    const float* __restrict__ dw2, const float* __restrict__ db2,
    float* __restrict__ out)
{
    extern __shared__ unsigned char sm[];
    int tid = threadIdx.x;
    int wid  = tid >> 5;
    int lane = tid & 31;

    for (int i = tid; i < 4096; i += 256) {
        int n = i >> 6, k = i & 63;
        float f = dw1[(64 + k) * 64 + n];
        __nv_bfloat16 h = __float2bfloat16(f);
        __nv_bfloat16 l = __float2bfloat16(f - __bfloat162float(h));
        *reinterpret_cast<__nv_bfloat16*>(sm + OFF_BH + n * 144 + k * 2) = h;
        *reinterpret_cast<__nv_bfloat16*>(sm + OFF_BL + n * 144 + k * 2) = l;
    }
    if (tid < 64) {
        reinterpret_cast<float*>(sm + OFF_DW2)[tid] = dw2[tid];
        reinterpret_cast<float*>(sm + OFF_DB1)[tid] = db1[tid];
    }

    {
        int half = lane >> 4;
        int c    = lane & 15;
        #pragma unroll
        for (int t = 0; t < 8; t++) {
            int p_local = wid * 16 + t * 2 + half;
            int p = blockIdx.x * 128 + p_local;
            int pc = p < PP ? p : PP - 1;
            int i0 = idx[pc];
            int j0 = idx[PP + pc];
            float4 hi4 = reinterpret_cast<const float4*>(g_h)[i0 * 16 + c];
            float4 hj4 = reinterpret_cast<const float4*>(g_h)[j0 * 16 + c];
            float4 pr = make_float4(hi4.x * hj4.x, hi4.y * hj4.y,
                                    hi4.z * hj4.z, hi4.w * hj4.w);
            uint2 ph, pl;
            split_pack(pr.x, pr.y, ph.x, pl.x);
            split_pack(pr.z, pr.w, ph.y, pl.y);
            *reinterpret_cast<uint2*>(sm + OFF_PH + p_local * 144 + c * 8) = ph;
            *reinterpret_cast<uint2*>(sm + OFF_PL + p_local * 144 + c * 8) = pl;
        }
    }
    __syncthreads();

    int grp  = lane >> 2;
    int tig  = lane & 3;
    int r0   = wid * 16 + grp;

    const uint32_t* PH  = reinterpret_cast<const uint32_t*>(sm + OFF_PH);
    const uint32_t* PL  = reinterpret_cast<const uint32_t*>(sm + OFF_PL);
    const uint32_t* BH  = reinterpret_cast<const uint32_t*>(sm + OFF_BH);
    const uint32_t* BL  = reinterpret_cast<const uint32_t*>(sm + OFF_BL);
    const float*   sdw2 = reinterpret_cast<const float*>(sm + OFF_DW2);
    const float*   sdb1 = reinterpret_cast<const float*>(sm + OFF_DB1);

    uint32_t ah[4][4], al[4][4];
    #pragma unroll
    for (int ks = 0; ks < 4; ks++) {
        int k0 = ks * 8 + tig;
        ah[ks][0] = PH[ r0      * 36 + k0];
        ah[ks][1] = PH[(r0 + 8) * 36 + k0];
        ah[ks][2] = PH[ r0      * 36 + k0 + 4];
        ah[ks][3] = PH[(r0 + 8) * 36 + k0 + 4];
        al[ks][0] = PL[ r0      * 36 + k0];
        al[ks][1] = PL[(r0 + 8) * 36 + k0];
        al[ks][2] = PL[ r0      * 36 + k0 + 4];
        al[ks][3] = PL[(r0 + 8) * 36 + k0 + 4];
    }

    int pA = blockIdx.x * 128 + r0;
    int pB = pA + 8;
    int pAc = pA < PP ? pA : PP - 1;
    int pBc = pB < PP ? pB : PP - 1;
    int iA = idx[pAc], jA = idx[PP + pAc];
    int iB = idx[pBc], jB = idx[PP + pBc];

    float pa = 0.0f, pb = 0.0f;
    #pragma unroll
    for (int nt = 0; nt < 8; nt++) {
        int n = nt * 8 + grp;
        int cbase = nt * 8 + tig * 2;
        float2 uA = *reinterpret_cast<const float2*>(&g_u[iA * 64 + cbase]);
        float2 vA = *reinterpret_cast<const float2*>(&g_v[jA * 64 + cbase]);
        float2 uB = *reinterpret_cast<const float2*>(&g_u[iB * 64 + cbase]);
        float2 vB = *reinterpret_cast<const float2*>(&g_v[jB * 64 + cbase]);
        float2 dbv = *reinterpret_cast<const float2*>(&sdb1[cbase]);
        float c0 = uA.x + vA.x + dbv.x, c1 = uA.y + vA.y + dbv.y;
        float c2 = uB.x + vB.x + dbv.x, c3 = uB.y + vB.y + dbv.y;
        #pragma unroll
        for (int ks = 0; ks < 4; ks++) {
            int kb = ks * 8 + tig;
            uint32_t bh0 = BH[n * 36 + kb], bh1 = BH[n * 36 + kb + 4];
            uint32_t bl0 = BL[n * 36 + kb], bl1 = BL[n * 36 + kb + 4];
            MMA16816(c0, c1, c2, c3, ah[ks], bh0, bh1);
            MMA16816(c0, c1, c2, c3, ah[ks], bl0, bl1);
            MMA16816(c0, c1, c2, c3, al[ks], bh0, bh1);
        }
        float w0 = sdw2[cbase], w1 = sdw2[cbase + 1];
        pa = fmaf(fmaxf(c0, 0.0f), w0, fmaf(fmaxf(c1, 0.0f), w1, pa));
        pb = fmaf(fmaxf(c2, 0.0f), w0, fmaf(fmaxf(c3, 0.0f), w1, pb));
    }

    pa += __shfl_xor_sync(0xffffffffu, pa, 1);
    pa += __shfl_xor_sync(0xffffffffu, pa, 2);
    pb += __shfl_xor_sync(0xffffffffu, pb, 1);
    pb += __shfl_xor_sync(0xffffffffu, pb, 2);

    if (tig == 0) {
        float bo = db2[0];
        if (pA < PP) out[pA] = pa + bo;
        if (pB < PP) out[pB] = pb + bo;
    }
}

// ---------------------------------------------------------------------------
extern "C" void kernel_launch(void* const* d_in, const int* in_sizes, int n_in,
                              void* d_out, int out_size) {
    const float* x   = (const float*)d_in[0];
    const int*   ei  = (const int*)  d_in[1];
    // d_in[2] = curvature (unused by the output)
    const int*   idx = (const int*)  d_in[3];
    const float* w1  = (const float*)d_in[4];
    const float* b1  = (const float*)d_in[5];
    const float* w2  = (const float*)d_in[6];
    const float* b2  = (const float*)d_in[7];
    const float* dw1 = (const float*)d_in[8];
    const float* db1 = (const float*)d_in[9];
    const float* dw2 = (const float*)d_in[10];
    const float* db2 = (const float*)d_in[11];
    float* out = (float*)d_out;

    cudaFuncSetAttribute(k_mlp_uv_mma, cudaFuncAttributeMaxDynamicSharedMemorySize,
                         MLP_SMEM);
    cudaFuncSetAttribute(k_pair_mma, cudaFuncAttributeMaxDynamicSharedMemorySize,
                         PAIR_SMEM);

    // CSR build
    k_zero <<<(NN + 256) / 256, 256>>>();
    k_count<<<(EE + 255) / 256, 256>>>(ei);
    k_scan1<<<NB, 1024>>>();
    k_scan2<<<1, 32>>>();
    k_scan3<<<(NN + 255) / 256, 256>>>();
    k_fill <<<(EE + 255) / 256, 256>>>(ei);

    // fused aggregate+node chain, then pair decoder
    k_mlp_uv_mma<<<296, 256, MLP_SMEM>>>(x, w1, b1, w2, b2, dw1);
    k_pair_mma  <<<(PP + 127) / 128, 256, PAIR_SMEM>>>(idx, dw1, db1, dw2, db2, out);
}

// round 17
// speedup vs baseline: 1.2872x; 1.2872x over previous
#include <cuda_runtime.h>
#include <cuda_bf16.h>
#include <cstdint>

#define NN 100000
#define EE 1600000
#define PP 200000
#define NTILES 782   // ceil(NN/128)
#define NB 98        // ceil(NN/1024) scan blocks

// Scratch (allocation-free rule: __device__ globals)
__device__ float g_h0[NN * 64];   // 2x + gather_sum
__device__ float g_h [NN * 64];   // node embedding after MLP
__device__ float g_u [NN * 64];   // h @ (A+C)
__device__ float g_v [NN * 64];   // h @ (A+D)
// CSR scratch
__device__ int g_deg[NN + 1];
__device__ int g_cur[NN + 1];
__device__ int g_off[NN + 1];
__device__ int g_adj[EE];
__device__ int g_blksum[NB];

// ---------------------------------------------------------------------------
// CSR build: zero -> count -> scan1 -> scan3(fused prefix) -> fill
__global__ void k_zero() {
    int i = blockIdx.x * blockDim.x + threadIdx.x;
    if (i <= NN) { g_deg[i] = 0; g_cur[i] = 0; }
}

__global__ void __launch_bounds__(256) k_count(const int* __restrict__ ei) {
    int e2 = blockIdx.x * blockDim.x + threadIdx.x;
    if (e2 * 2 >= EE) return;
    int2 d = reinterpret_cast<const int2*>(ei + EE)[e2];
    atomicAdd(&g_deg[d.x], 1);
    if (e2 * 2 + 1 < EE) atomicAdd(&g_deg[d.y], 1);
}

__global__ void __launch_bounds__(1024) k_scan1() {
    __shared__ int s[1024];
    int t = threadIdx.x;
    int i = blockIdx.x * 1024 + t;
    int v = (i < NN) ? g_deg[i] : 0;
    s[t] = v;
    __syncthreads();
    #pragma unroll
    for (int o = 1; o < 1024; o <<= 1) {
        int tv = (t >= o) ? s[t - o] : 0;
        __syncthreads();
        s[t] += tv;
        __syncthreads();
    }
    if (i < NN) g_off[i] = s[t] - v;          // block-local exclusive
    if (t == 1023) g_blksum[blockIdx.x] = s[t];
}

// fused: each block computes its own exclusive block-prefix (<=98 loads) and
// applies it. Eliminates the serial k_scan2 launch.
__global__ void __launch_bounds__(1024) k_scan3() {
    __shared__ int spre;
    int b = blockIdx.x, t = threadIdx.x;
    if (t < 32) {
        int acc = 0;
        for (int j = t; j < b; j += 32) acc += g_blksum[j];
        #pragma unroll
        for (int o = 16; o > 0; o >>= 1)
            acc += __shfl_down_sync(0xffffffffu, acc, o);
        if (t == 0) spre = acc;
    }
    __syncthreads();
    int i = b * 1024 + t;
    if (i < NN) g_off[i] += spre;
    if (i == 0) g_off[NN] = EE;
}

__global__ void __launch_bounds__(256) k_fill(const int* __restrict__ ei) {
    int e2 = blockIdx.x * blockDim.x + threadIdx.x;
    if (e2 * 2 >= EE) return;
    int2 s = reinterpret_cast<const int2*>(ei)[e2];
    int2 d = reinterpret_cast<const int2*>(ei + EE)[e2];
    int pos = atomicAdd(&g_cur[d.x], 1);
    g_adj[g_off[d.x] + pos] = s.x;
    if (e2 * 2 + 1 < EE) {
        int pos2 = atomicAdd(&g_cur[d.y], 1);
        g_adj[g_off[d.y] + pos2] = s.y;
    }
}

// ---------------------------------------------------------------------------
// K1: aggregation as gather: h0[n] = 2*x[n] + sum_{s in adj(n)} x[s]
// Half-warp per node; lane c owns float4 chunk c. adj batched 16-wide and
// broadcast via shfl within the half-warp.
__global__ void __launch_bounds__(256) k_agg(const float* __restrict__ x) {
    int hw = blockIdx.x * 16 + (threadIdx.x >> 4);
    int c  = threadIdx.x & 15;
    if (hw >= NN) return;
    unsigned hm = 0xFFFFu << (threadIdx.x & 16);

    const float4* x4 = reinterpret_cast<const float4*>(x);
    float4 acc = x4[hw * 16 + c];
    acc.x += acc.x; acc.y += acc.y; acc.z += acc.z; acc.w += acc.w;

    int off0 = g_off[hw];
    int off1 = g_off[hw + 1];
    for (int base = off0; base < off1; base += 16) {
        int idxv = (base + c < off1) ? g_adj[base + c] : 0;
        int cnt  = off1 - base; if (cnt > 16) cnt = 16;
        #pragma unroll 4
        for (int t = 0; t < cnt; t++) {
            int s = __shfl_sync(hm, idxv, t, 16);
            float4 v = x4[s * 16 + c];
            acc.x += v.x; acc.y += v.y; acc.z += v.z; acc.w += v.w;
        }
    }
    reinterpret_cast<float4*>(g_h0)[hw * 16 + c] = acc;
}

// ---------------------------------------------------------------------------
// shared MMA helpers
__device__ __forceinline__ void split_pack(float fx, float fy, uint32_t& hi, uint32_t& lo) {
    __nv_bfloat16 hx = __float2bfloat16(fx);
    __nv_bfloat16 hy = __float2bfloat16(fy);
    __nv_bfloat16 lx = __float2bfloat16(fx - __bfloat162float(hx));
    __nv_bfloat16 ly = __float2bfloat16(fy - __bfloat162float(hy));
    __nv_bfloat162 h2; h2.x = hx; h2.y = hy;
    __nv_bfloat162 l2; l2.x = lx; l2.y = ly;
    hi = *reinterpret_cast<uint32_t*>(&h2);
    lo = *reinterpret_cast<uint32_t*>(&l2);
}

__device__ __forceinline__ void split_sts(unsigned char* sm, int offH, int offL,
                                          int byte_off, float f) {
    __nv_bfloat16 h = __float2bfloat16(f);
    __nv_bfloat16 l = __float2bfloat16(f - __bfloat162float(h));
    *reinterpret_cast<__nv_bfloat16*>(sm + offH + byte_off) = h;
    *reinterpret_cast<__nv_bfloat16*>(sm + offL + byte_off) = l;
}

#define MMA16816(c0, c1, c2, c3, a, b0, b1)                                  \
    asm volatile(                                                            \
        "mma.sync.aligned.m16n8k16.row.col.f32.bf16.bf16.f32 "              \
        "{%0,%1,%2,%3}, {%4,%5,%6,%7}, {%8,%9}, {%0,%1,%2,%3};"             \
        : "+f"(c0), "+f"(c1), "+f"(c2), "+f"(c3)                             \
        : "r"((a)[0]), "r"((a)[1]), "r"((a)[2]), "r"((a)[3]),                \
          "r"(b0), "r"(b1))

// ===========================================================================
// K2: node chain on warp-level bf16 MMA (R15 structure — standalone agg).
// ===========================================================================

#define MOFF_W1H 0
#define MOFF_W1L 9216
#define MOFF_W2H 18432
#define MOFF_W2L 27648
#define MOFF_ACH 36864
#define MOFF_ACL 46080
#define MOFF_ADH 55296
#define MOFF_ADL 64512
#define MOFF_A   73728
#define MOFF_B1  110592
#define MOFF_B2  110848
#define MLP_SMEM 111104

#define MMA_LAYER(D, WH, WL)                                                 \
    _Pragma("unroll")                                                        \
    for (int nt = 0; nt < 8; nt++) {                                         \
        int n = nt * 8 + grp;                                                \
        _Pragma("unroll")                                                    \
        for (int ks = 0; ks < 4; ks++) {                                     \
            int kb = ks * 8 + tig;                                           \
            uint32_t bh0 = (WH)[n * 36 + kb], bh1 = (WH)[n * 36 + kb + 4];   \
            uint32_t bl0 = (WL)[n * 36 + kb], bl1 = (WL)[n * 36 + kb + 4];   \
            MMA16816(D[nt].x, D[nt].y, D[nt].z, D[nt].w, ah[ks], bh0, bh1);  \
            MMA16816(D[nt].x, D[nt].y, D[nt].z, D[nt].w, ah[ks], bl0, bl1);  \
            MMA16816(D[nt].x, D[nt].y, D[nt].z, D[nt].w, al[ks], bh0, bh1);  \
        }                                                                    \
    }

#define REPACK_FRAGS(D)                                                      \
    _Pragma("unroll")                                                        \
    for (int ks = 0; ks < 4; ks++) {                                         \
        split_pack(D[2*ks].x,   D[2*ks].y,   ah[ks][0], al[ks][0]);          \
        split_pack(D[2*ks].z,   D[2*ks].w,   ah[ks][1], al[ks][1]);          \
        split_pack(D[2*ks+1].x, D[2*ks+1].y, ah[ks][2], al[ks][2]);          \
        split_pack(D[2*ks+1].z, D[2*ks+1].w, ah[ks][3], al[ks][3]);          \
    }

#define STORE_ROWS(dst, D)                                                   \
    _Pragma("unroll")                                                        \
    for (int nt = 0; nt < 8; nt++) {                                         \
        int cbase = nt * 8 + tig * 2;                                        \
        if (nodeA < NN)                                                      \
            *reinterpret_cast<float2*>(&dst[nodeA * 64 + cbase]) =           \
                make_float2(D[nt].x, D[nt].y);                               \
        if (nodeB < NN)                                                      \
            *reinterpret_cast<float2*>(&dst[nodeB * 64 + cbase]) =           \
                make_float2(D[nt].z, D[nt].w);                               \
    }

__global__ void __launch_bounds__(256) k_mlp_uv_mma(
    const float* __restrict__ w1, const float* __restrict__ b1,
    const float* __restrict__ w2, const float* __restrict__ b2,
    const float* __restrict__ dw1)
{
    extern __shared__ unsigned char sm[];
    int tid  = threadIdx.x;
    int wid  = tid >> 5;
    int lane = tid & 31;

    for (int i = tid; i < 4096; i += 256) {
        int n = i & 63, k = i >> 6;
        int bo = n * 144 + k * 2;
        float fa = dw1[k * 64 + n];
        split_sts(sm, MOFF_W1H, MOFF_W1L, bo, w1[k * 64 + n]);
        split_sts(sm, MOFF_W2H, MOFF_W2L, bo, w2[k * 64 + n]);
        split_sts(sm, MOFF_ACH, MOFF_ACL, bo, fa + dw1[(128 + k) * 64 + n]);
        split_sts(sm, MOFF_ADH, MOFF_ADL, bo, fa + dw1[(192 + k) * 64 + n]);
    }
    if (tid < 64) {
        reinterpret_cast<float*>(sm + MOFF_B1)[tid] = b1[tid];
        reinterpret_cast<float*>(sm + MOFF_B2)[tid] = b2[tid];
    }
    __syncthreads();

    const uint32_t* W1H = reinterpret_cast<const uint32_t*>(sm + MOFF_W1H);
    const uint32_t* W1L = reinterpret_cast<const uint32_t*>(sm + MOFF_W1L);
    const uint32_t* W2H = reinterpret_cast<const uint32_t*>(sm + MOFF_W2H);
    const uint32_t* W2L = reinterpret_cast<const uint32_t*>(sm + MOFF_W2L);
    const uint32_t* ACH = reinterpret_cast<const uint32_t*>(sm + MOFF_ACH);
    const uint32_t* ACL = reinterpret_cast<const uint32_t*>(sm + MOFF_ACL);
    const uint32_t* ADH = reinterpret_cast<const uint32_t*>(sm + MOFF_ADH);
    const uint32_t* ADL = reinterpret_cast<const uint32_t*>(sm + MOFF_ADL);
    const float* sb1 = reinterpret_cast<const float*>(sm + MOFF_B1);
    const float* sb2 = reinterpret_cast<const float*>(sm + MOFF_B2);

    unsigned char* Awarp = sm + MOFF_A + wid * 4608;
    const uint32_t* AH = reinterpret_cast<const uint32_t*>(Awarp);
    const uint32_t* AL = reinterpret_cast<const uint32_t*>(Awarp + 2304);

    int grp = lane >> 2;
    int tig = lane & 3;
    int half = lane >> 4;
    int c    = lane & 15;

    for (int tile = blockIdx.x; tile < NTILES; tile += gridDim.x) {
        #pragma unroll
        for (int t = 0; t < 8; t++) {
            int rw = t * 2 + half;
            int node = tile * 128 + wid * 16 + rw;
            int nc = node < NN ? node : NN - 1;
            float4 v = reinterpret_cast<const float4*>(g_h0)[nc * 16 + c];
            uint32_t h0, l0, h1, l1;
            split_pack(v.x, v.y, h0, l0);
            split_pack(v.z, v.w, h1, l1);
            *reinterpret_cast<uint2*>(Awarp + rw * 144 + c * 8)        = make_uint2(h0, h1);
            *reinterpret_cast<uint2*>(Awarp + 2304 + rw * 144 + c * 8) = make_uint2(l0, l1);
        }
        __syncwarp();

        uint32_t ah[4][4], al[4][4];
        #pragma unroll
        for (int ks = 0; ks < 4; ks++) {
            int k0 = ks * 8 + tig;
            ah[ks][0] = AH[ grp      * 36 + k0];
            ah[ks][1] = AH[(grp + 8) * 36 + k0];
            ah[ks][2] = AH[ grp      * 36 + k0 + 4];
            ah[ks][3] = AH[(grp + 8) * 36 + k0 + 4];
            al[ks][0] = AL[ grp      * 36 + k0];
            al[ks][1] = AL[(grp + 8) * 36 + k0];
            al[ks][2] = AL[ grp      * 36 + k0 + 4];
            al[ks][3] = AL[(grp + 8) * 36 + k0 + 4];
        }
        __syncwarp();

        int nodeA = tile * 128 + wid * 16 + grp;
        int nodeB = nodeA + 8;
        float4 D[8];

        #pragma unroll
        for (int nt = 0; nt < 8; nt++) {
            int cbase = nt * 8 + tig * 2;
            float bx = sb1[cbase], by = sb1[cbase + 1];
            D[nt] = make_float4(bx, by, bx, by);
        }
        MMA_LAYER(D, W1H, W1L)
        #pragma unroll
        for (int nt = 0; nt < 8; nt++) {
            D[nt].x = fmaxf(D[nt].x, 0.0f); D[nt].y = fmaxf(D[nt].y, 0.0f);
            D[nt].z = fmaxf(D[nt].z, 0.0f); D[nt].w = fmaxf(D[nt].w, 0.0f);
        }
        REPACK_FRAGS(D)

        #pragma unroll
        for (int nt = 0; nt < 8; nt++) {
            int cbase = nt * 8 + tig * 2;
            float bx = sb2[cbase], by = sb2[cbase + 1];
            D[nt] = make_float4(bx, by, bx, by);
        }
        MMA_LAYER(D, W2H, W2L)
        #pragma unroll
        for (int nt = 0; nt < 8; nt++) {
            D[nt].x = fmaxf(D[nt].x, 0.0f); D[nt].y = fmaxf(D[nt].y, 0.0f);
            D[nt].z = fmaxf(D[nt].z, 0.0f); D[nt].w = fmaxf(D[nt].w, 0.0f);
        }
        STORE_ROWS(g_h, D)
        REPACK_FRAGS(D)

        #pragma unroll
        for (int nt = 0; nt < 8; nt++) D[nt] = make_float4(0.f, 0.f, 0.f, 0.f);
        MMA_LAYER(D, ACH, ACL)
        STORE_ROWS(g_u, D)

        #pragma unroll
        for (int nt = 0; nt < 8; nt++) D[nt] = make_float4(0.f, 0.f, 0.f, 0.f);
        MMA_LAYER(D, ADH, ADL)
        STORE_ROWS(g_v, D)
    }
}

// ===========================================================================
// K3: pair decoder (unchanged from R15).
// ===========================================================================

#define OFF_PH  0
#define OFF_PL  18432
#define OFF_BH  36864
#define OFF_BL  46080
#define OFF_DW2 55296
#define OFF_DB1 55552
#define PAIR_SMEM 55808

__global__ void __launch_bounds__(256) k_pair_mma(
    const int* __restrict__ idx,
    const float* __restrict__ dw1, const float* __restrict__ db1,
    const float* __restrict__ dw2, const float* __restrict__ db2,
    float* __restrict__ out)
{
    extern __shared__ unsigned char sm[];
    int tid = threadIdx.x;
    int wid  = tid >> 5;
    int lane = tid & 31;

    for (int i = tid; i < 4096; i += 256) {
        int n = i >> 6, k = i & 63;
        float f = dw1[(64 + k) * 64 + n];
        __nv_bfloat16 h = __float2bfloat16(f);
        __nv_bfloat16 l = __float2bfloat16(f - __bfloat162float(h));
        *reinterpret_cast<__nv_bfloat16*>(sm + OFF_BH + n * 144 + k * 2) = h;
        *reinterpret_cast<__nv_bfloat16*>(sm + OFF_BL + n * 144 + k * 2) = l;
    }
    if (tid < 64) {
        reinterpret_cast<float*>(sm + OFF_DW2)[tid] = dw2[tid];
        reinterpret_cast<float*>(sm + OFF_DB1)[tid] = db1[tid];
    }

    {
        int half = lane >> 4;
        int c    = lane & 15;
        #pragma unroll
        for (int t = 0; t < 8; t++) {
            int p_local = wid * 16 + t * 2 + half;
            int p = blockIdx.x * 128 + p_local;
            int pc = p < PP ? p : PP - 1;
            int i0 = idx[pc];
            int j0 = idx[PP + pc];
            float4 hi4 = reinterpret_cast<const float4*>(g_h)[i0 * 16 + c];
            float4 hj4 = reinterpret_cast<const float4*>(g_h)[j0 * 16 + c];
            float4 pr = make_float4(hi4.x * hj4.x, hi4.y * hj4.y,
                                    hi4.z * hj4.z, hi4.w * hj4.w);
            uint2 ph, pl;
            split_pack(pr.x, pr.y, ph.x, pl.x);
            split_pack(pr.z, pr.w, ph.y, pl.y);
            *reinterpret_cast<uint2*>(sm + OFF_PH + p_local * 144 + c * 8) = ph;
            *reinterpret_cast<uint2*>(sm + OFF_PL + p_local * 144 + c * 8) = pl;
        }
    }
    __syncthreads();

    int grp  = lane >> 2;
    int tig  = lane & 3;
    int r0   = wid * 16 + grp;

    const uint32_t* PH  = reinterpret_cast<const uint32_t*>(sm + OFF_PH);
    const uint32_t* PL  = reinterpret_cast<const uint32_t*>(sm + OFF_PL);
    const uint32_t* BH  = reinterpret_cast<const uint32_t*>(sm + OFF_BH);
    const uint32_t* BL  = reinterpret_cast<const uint32_t*>(sm + OFF_BL);
    const float*   sdw2 = reinterpret_cast<const float*>(sm + OFF_DW2);
    const float*   sdb1 = reinterpret_cast<const float*>(sm + OFF_DB1);

    uint32_t ah[4][4], al[4][4];
    #pragma unroll
    for (int ks = 0; ks < 4; ks++) {
        int k0 = ks * 8 + tig;
        ah[ks][0] = PH[ r0      * 36 + k0];
        ah[ks][1] = PH[(r0 + 8) * 36 + k0];
        ah[ks][2] = PH[ r0      * 36 + k0 + 4];
        ah[ks][3] = PH[(r0 + 8) * 36 + k0 + 4];
        al[ks][0] = PL[ r0      * 36 + k0];
        al[ks][1] = PL[(r0 + 8) * 36 + k0];
        al[ks][2] = PL[ r0      * 36 + k0 + 4];
        al[ks][3] = PL[(r0 + 8) * 36 + k0 + 4];
    }

    int pA = blockIdx.x * 128 + r0;
    int pB = pA + 8;
    int pAc = pA < PP ? pA : PP - 1;
    int pBc = pB < PP ? pB : PP - 1;
    int iA = idx[pAc], jA = idx[PP + pAc];
    int iB = idx[pBc], jB = idx[PP + pBc];

    float pa = 0.0f, pb = 0.0f;
    #pragma unroll
    for (int nt = 0; nt < 8; nt++) {
        int n = nt * 8 + grp;
        int cbase = nt * 8 + tig * 2;
        float2 uA = *reinterpret_cast<const float2*>(&g_u[iA * 64 + cbase]);
        float2 vA = *reinterpret_cast<const float2*>(&g_v[jA * 64 + cbase]);
        float2 uB = *reinterpret_cast<const float2*>(&g_u[iB * 64 + cbase]);
        float2 vB = *reinterpret_cast<const float2*>(&g_v[jB * 64 + cbase]);
        float2 dbv = *reinterpret_cast<const float2*>(&sdb1[cbase]);
        float c0 = uA.x + vA.x + dbv.x, c1 = uA.y + vA.y + dbv.y;
        float c2 = uB.x + vB.x + dbv.x, c3 = uB.y + vB.y + dbv.y;
        #pragma unroll
        for (int ks = 0; ks < 4; ks++) {
            int kb = ks * 8 + tig;
            uint32_t bh0 = BH[n * 36 + kb], bh1 = BH[n * 36 + kb + 4];
            uint32_t bl0 = BL[n * 36 + kb], bl1 = BL[n * 36 + kb + 4];
            MMA16816(c0, c1, c2, c3, ah[ks], bh0, bh1);
            MMA16816(c0, c1, c2, c3, ah[ks], bl0, bl1);
            MMA16816(c0, c1, c2, c3, al[ks], bh0, bh1);
        }
        float w0 = sdw2[cbase], w1 = sdw2[cbase + 1];
        pa = fmaf(fmaxf(c0, 0.0f), w0, fmaf(fmaxf(c1, 0.0f), w1, pa));
        pb = fmaf(fmaxf(c2, 0.0f), w0, fmaf(fmaxf(c3, 0.0f), w1, pb));
    }

    pa += __shfl_xor_sync(0xffffffffu, pa, 1);
    pa += __shfl_xor_sync(0xffffffffu, pa, 2);
    pb += __shfl_xor_sync(0xffffffffu, pb, 1);
    pb += __shfl_xor_sync(0xffffffffu, pb, 2);

    if (tig == 0) {
        float bo = db2[0];
        if (pA < PP) out[pA] = pa + bo;
        if (pB < PP) out[pB] = pb + bo;
    }
}

// ---------------------------------------------------------------------------
extern "C" void kernel_launch(void* const* d_in, const int* in_sizes, int n_in,
                              void* d_out, int out_size) {
    const float* x   = (const float*)d_in[0];
    const int*   ei  = (const int*)  d_in[1];
    // d_in[2] = curvature (unused by the output)
    const int*   idx = (const int*)  d_in[3];
    const float* w1  = (const float*)d_in[4];
    const float* b1  = (const float*)d_in[5];
    const float* w2  = (const float*)d_in[6];
    const float* b2  = (const float*)d_in[7];
    const float* dw1 = (const float*)d_in[8];
    const float* db1 = (const float*)d_in[9];
    const float* dw2 = (const float*)d_in[10];
    const float* db2 = (const float*)d_in[11];
    float* out = (float*)d_out;

    cudaFuncSetAttribute(k_mlp_uv_mma, cudaFuncAttributeMaxDynamicSharedMemorySize,
                         MLP_SMEM);
    cudaFuncSetAttribute(k_pair_mma, cudaFuncAttributeMaxDynamicSharedMemorySize,
                         PAIR_SMEM);

    // CSR build (scan2 folded into scan3; count/fill 2 edges per thread)
    k_zero <<<(NN + 256) / 256, 256>>>();
    k_count<<<(EE / 2 + 255) / 256, 256>>>(ei);
    k_scan1<<<NB, 1024>>>();
    k_scan3<<<NB, 1024>>>();
    k_fill <<<(EE / 2 + 255) / 256, 256>>>(ei);

    // aggregate + node chain + pair decoder (R15 structure)
    k_agg       <<<(NN + 15) / 16, 256>>>(x);
    k_mlp_uv_mma<<<296, 256, MLP_SMEM>>>(w1, b1, w2, b2, dw1);
    k_pair_mma  <<<(PP + 127) / 128, 256, PAIR_SMEM>>>(idx, dw1, db1, dw2, db2, out);
}